// round 1
// baseline (speedup 1.0000x reference)
#include <cuda_runtime.h>
#include <cuda_bf16.h>
#include <cstdint>

#define NN 4096
#define CC 256      // IN_DIM = OUT_DIM = 256
#define HH 4
#define DD 64
#define ALPHA 0.2f
#define TI 16
#define TJ 64

// Scratch (device globals: no allocation allowed)
__device__ float g_Wh[NN * CC];
__device__ float g_src[NN * HH];
__device__ float g_dst[NN * HH];
__device__ float g_gdmax[HH];

// ---------------------------------------------------------------------------
// Kernel 1: Wh = h @ W^T + b      h:[N,256]  W:[256,256] row-major (out,in)
// 64x64 output tile per block, 256 threads, 4x4 microtile per thread.
// ---------------------------------------------------------------------------
__global__ __launch_bounds__(256) void gemm_kernel(const float* __restrict__ h,
                                                   const float* __restrict__ W,
                                                   const float* __restrict__ b) {
    __shared__ float hs[64][36];
    __shared__ float ws[64][36];
    const int row0 = blockIdx.x * 64;
    const int col0 = blockIdx.y * 64;
    const int t = threadIdx.x;
    const int tx = t & 15, ty = t >> 4;

    float acc[4][4];
#pragma unroll
    for (int i = 0; i < 4; i++)
#pragma unroll
        for (int j = 0; j < 4; j++) acc[i][j] = 0.f;

    for (int k0 = 0; k0 < CC; k0 += 32) {
        const int r = t >> 3, kq = (t & 7) * 4;
        *(float4*)&hs[r][kq]      = *(const float4*)&h[(size_t)(row0 + r) * CC + k0 + kq];
        *(float4*)&hs[r + 32][kq] = *(const float4*)&h[(size_t)(row0 + r + 32) * CC + k0 + kq];
        *(float4*)&ws[r][kq]      = *(const float4*)&W[(size_t)(col0 + r) * CC + k0 + kq];
        *(float4*)&ws[r + 32][kq] = *(const float4*)&W[(size_t)(col0 + r + 32) * CC + k0 + kq];
        __syncthreads();
#pragma unroll
        for (int kk = 0; kk < 32; kk++) {
            float hv[4], wv[4];
#pragma unroll
            for (int i = 0; i < 4; i++) hv[i] = hs[ty * 4 + i][kk];
#pragma unroll
            for (int j = 0; j < 4; j++) wv[j] = ws[tx * 4 + j][kk];
#pragma unroll
            for (int i = 0; i < 4; i++)
#pragma unroll
                for (int j = 0; j < 4; j++) acc[i][j] = fmaf(hv[i], wv[j], acc[i][j]);
        }
        __syncthreads();
    }
#pragma unroll
    for (int i = 0; i < 4; i++) {
#pragma unroll
        for (int j = 0; j < 4; j++) {
            const int c = col0 + tx * 4 + j;
            g_Wh[(size_t)(row0 + ty * 4 + i) * CC + c] = acc[i][j] + b[c];
        }
    }
}

// ---------------------------------------------------------------------------
// Kernel 2: src[n,h] = Wh[n,h,:] . a[h,0:64] ; dst[n,h] = Wh[n,h,:] . a[h,64:128]
// One warp per row.
// ---------------------------------------------------------------------------
__global__ __launch_bounds__(256) void srcdst_kernel(const float* __restrict__ a) {
    const int n = blockIdx.x * 8 + (threadIdx.x >> 5);
    const int l = threadIdx.x & 31;
#pragma unroll
    for (int h = 0; h < HH; h++) {
        float s = 0.f, dd = 0.f;
#pragma unroll
        for (int q = 0; q < 2; q++) {
            const int d = l + q * 32;
            const float w = g_Wh[(size_t)n * CC + h * DD + d];
            s  = fmaf(w, a[h * 128 + d], s);
            dd = fmaf(w, a[h * 128 + 64 + d], dd);
        }
#pragma unroll
        for (int off = 16; off > 0; off >>= 1) {
            s  += __shfl_xor_sync(0xFFFFFFFFu, s, off);
            dd += __shfl_xor_sync(0xFFFFFFFFu, dd, off);
        }
        if (l == 0) { g_src[n * HH + h] = s; g_dst[n * HH + h] = dd; }
    }
}

// ---------------------------------------------------------------------------
// Kernel 3: gdmax[h] = max_n dst[n,h]   (single block)
// ---------------------------------------------------------------------------
__global__ __launch_bounds__(256) void gdmax_kernel() {
    __shared__ float red[256];
    const int t = threadIdx.x;
    const int h = t & 3;
    float m = -3.4e38f;
    for (int n = t >> 2; n < NN; n += 64) m = fmaxf(m, g_dst[n * HH + h]);
    red[t] = m;
    __syncthreads();
#pragma unroll
    for (int s = 128; s >= 4; s >>= 1) {
        if (t < s) red[t] = fmaxf(red[t], red[t + s]);
        __syncthreads();
    }
    if (t < 4) g_gdmax[t] = red[t];
}

// ---------------------------------------------------------------------------
// Kernel 4: fused attention.
// Block: TI=16 rows i, 256 threads. j swept in tiles of TJ=64.
// m_i = leakyrelu(src_i + gdmax)  (valid softmax max upper bound: leakyrelu is
// monotone and dst_j <= gdmax), so NO online rescaling is needed.
// Stage A: p[jj][h][il] = adj ? exp(lrelu(src+dst)-m) : 0   (smem)
// Stage B: per thread (il_g,hh,dg): acc[4il][4d] += p * Wh   (2x LDS.128 + 16 FFMA / jj)
//   wh_s read: jj*256 + hh*64 + dg*4 -> warp spans 512B contiguous: conflict-free
//   p_s  read: jj*64  + hh*16 + il_g*4 -> 2 distinct 16B addrs/warp: broadcast
// ---------------------------------------------------------------------------
__global__ __launch_bounds__(256, 2) void attn_kernel(const int* __restrict__ adj,
                                                      float* __restrict__ out) {
    extern __shared__ float sm[];
    float* wh_s  = sm;                       // 16384 floats (64KB)
    float* p_s   = sm + 16384;               // 4096
    int*   adj_s = (int*)(sm + 20480);       // 1024
    float* dst_s = sm + 21504;               // 256
    float* ms    = sm + 21760;               // 64
    float* srcs  = sm + 21824;               // 64
    float* lred  = sm + 21888;               // 256
    float* ls    = sm + 22144;               // 64   -> total 22208 floats

    const int t  = threadIdx.x;
    const int i0 = blockIdx.x * TI;

    if (t < 64) {
        const int il = t >> 2, h = t & 3;
        const float s = g_src[(i0 + il) * HH + h];
        srcs[t] = s;
        const float mm = s + g_gdmax[h];
        ms[t] = mm > 0.f ? mm : ALPHA * mm;
    }
    // stage-B identity
    const int il_g = t >> 6, hh = (t >> 4) & 3, dg = t & 15;
    // stage-A identity (fixed per thread; its 16 values share (il,h), span jj)
    const int ilA = t & 15, hA = (t >> 4) & 3, jjA = t >> 6;

    float acc[4][4];
#pragma unroll
    for (int i = 0; i < 4; i++)
#pragma unroll
        for (int j = 0; j < 4; j++) acc[i][j] = 0.f;
    float lsum = 0.f;

    __syncthreads();
    const float sA = srcs[ilA * 4 + hA];
    const float mA = ms[ilA * 4 + hA];

    for (int j0 = 0; j0 < NN; j0 += TJ) {
        __syncthreads();  // previous stage B done before overwrite
        // load Wh tile (64KB), coalesced float4
#pragma unroll
        for (int q = 0; q < 16; q++) {
            const int idx = (t + q * 256) * 4;
            *(float4*)&wh_s[idx] = *(const float4*)&g_Wh[(size_t)j0 * CC + idx];
        }
        // dst tile (contiguous)
        dst_s[t] = g_dst[j0 * HH + t];
        // adj tile, transposed store adj_s[jj*16+il]
#pragma unroll
        for (int q = 0; q < 4; q++) {
            const int idx = t + q * 256;
            const int il = idx >> 6, jj = idx & 63;
            adj_s[jj * 16 + il] = adj[(size_t)(i0 + il) * NN + j0 + jj];
        }
        __syncthreads();
        // stage A: probabilities
#pragma unroll
        for (int k = 0; k < 16; k++) {
            const int jj = jjA + 4 * k;
            const int av = adj_s[jj * 16 + ilA];
            float e = sA + dst_s[jj * 4 + hA];
            e = e > 0.f ? e : ALPHA * e;
            const float p = av ? __expf(e - mA) : 0.f;
            p_s[(jj * 4 + hA) * 16 + ilA] = p;
            lsum += p;
        }
        __syncthreads();
        // stage B: accumulate
#pragma unroll 16
        for (int jj = 0; jj < TJ; jj++) {
            const float4 wv = *(const float4*)&wh_s[jj * 256 + hh * 64 + dg * 4];
            const float4 pv = *(const float4*)&p_s[(jj * 4 + hh) * 16 + il_g * 4];
            acc[0][0] = fmaf(pv.x, wv.x, acc[0][0]);
            acc[0][1] = fmaf(pv.x, wv.y, acc[0][1]);
            acc[0][2] = fmaf(pv.x, wv.z, acc[0][2]);
            acc[0][3] = fmaf(pv.x, wv.w, acc[0][3]);
            acc[1][0] = fmaf(pv.y, wv.x, acc[1][0]);
            acc[1][1] = fmaf(pv.y, wv.y, acc[1][1]);
            acc[1][2] = fmaf(pv.y, wv.z, acc[1][2]);
            acc[1][3] = fmaf(pv.y, wv.w, acc[1][3]);
            acc[2][0] = fmaf(pv.z, wv.x, acc[2][0]);
            acc[2][1] = fmaf(pv.z, wv.y, acc[2][1]);
            acc[2][2] = fmaf(pv.z, wv.z, acc[2][2]);
            acc[2][3] = fmaf(pv.z, wv.w, acc[2][3]);
            acc[3][0] = fmaf(pv.w, wv.x, acc[3][0]);
            acc[3][1] = fmaf(pv.w, wv.y, acc[3][1]);
            acc[3][2] = fmaf(pv.w, wv.z, acc[3][2]);
            acc[3][3] = fmaf(pv.w, wv.w, acc[3][3]);
        }
    }

    // reduce l over the 4 jj-phase partials per (il,h)
    __syncthreads();
    lred[t] = lsum;
    __syncthreads();
    if (t < 64) ls[t] = lred[t] + lred[t + 64] + lred[t + 128] + lred[t + 192];
    __syncthreads();

#pragma unroll
    for (int a2 = 0; a2 < 4; a2++) {
        const int il = il_g * 4 + a2;
        const float inv = 1.0f / ls[(hh << 4) + il];
        float4 o;
        o.x = acc[a2][0] * inv;
        o.y = acc[a2][1] * inv;
        o.z = acc[a2][2] * inv;
        o.w = acc[a2][3] * inv;
        *(float4*)&out[(size_t)(i0 + il) * CC + hh * 64 + dg * 4] = o;
    }
}

// ---------------------------------------------------------------------------
extern "C" void kernel_launch(void* const* d_in, const int* in_sizes, int n_in,
                              void* d_out, int out_size) {
    const float* h   = (const float*)d_in[0];
    const int*   adj = (const int*)d_in[1];
    const float* W   = (const float*)d_in[2];
    const float* b   = (const float*)d_in[3];
    const float* a   = (const float*)d_in[4];
    float* out = (float*)d_out;

    const int attn_smem = 22208 * (int)sizeof(float);  // ~86.8KB
    cudaFuncSetAttribute(attn_kernel, cudaFuncAttributeMaxDynamicSharedMemorySize, attn_smem);

    gemm_kernel<<<dim3(NN / 64, CC / 64), 256>>>(h, W, b);
    srcdst_kernel<<<NN / 8, 256>>>(a);
    gdmax_kernel<<<1, 256>>>();
    attn_kernel<<<NN / TI, 256, attn_smem>>>(adj, out);
}

// round 2
// speedup vs baseline: 1.0818x; 1.0818x over previous
#include <cuda_runtime.h>
#include <cuda_bf16.h>
#include <cstdint>

#define NN 4096
#define CC 256      // IN_DIM = OUT_DIM = 256
#define HH 4
#define DD 64
#define ALPHA 0.2f
#define TI 32
#define TJ 64

// Scratch (device globals: no allocation allowed)
__device__ float g_Wh[NN * CC];
__device__ float g_src[NN * HH];
__device__ float g_dst[NN * HH];
__device__ float g_gdmax[HH];

// ---------------------------------------------------------------------------
// f32x2 packed-math helpers (sm_103a)
// ---------------------------------------------------------------------------
__device__ __forceinline__ uint64_t pack2(float lo, float hi) {
    uint64_t r; asm("mov.b64 %0, {%1,%2};" : "=l"(r) : "f"(lo), "f"(hi)); return r;
}
__device__ __forceinline__ uint64_t dup2(float v) {
    uint64_t r; asm("mov.b64 %0, {%1,%1};" : "=l"(r) : "f"(v)); return r;
}
__device__ __forceinline__ void ffma2(uint64_t& d, uint64_t a, uint64_t b) {
    asm("fma.rn.f32x2 %0, %1, %2, %0;" : "+l"(d) : "l"(a), "l"(b));
}
__device__ __forceinline__ float2 unpack2(uint64_t v) {
    float2 f; asm("mov.b64 {%0,%1}, %2;" : "=f"(f.x), "=f"(f.y) : "l"(v)); return f;
}

// ---------------------------------------------------------------------------
// Kernel 1: Wh = h @ W^T + b
// ---------------------------------------------------------------------------
__global__ __launch_bounds__(256) void gemm_kernel(const float* __restrict__ h,
                                                   const float* __restrict__ W,
                                                   const float* __restrict__ b) {
    __shared__ float hs[64][36];
    __shared__ float ws[64][36];
    const int row0 = blockIdx.x * 64;
    const int col0 = blockIdx.y * 64;
    const int t = threadIdx.x;
    const int tx = t & 15, ty = t >> 4;

    float acc[4][4];
#pragma unroll
    for (int i = 0; i < 4; i++)
#pragma unroll
        for (int j = 0; j < 4; j++) acc[i][j] = 0.f;

    for (int k0 = 0; k0 < CC; k0 += 32) {
        const int r = t >> 3, kq = (t & 7) * 4;
        *(float4*)&hs[r][kq]      = *(const float4*)&h[(size_t)(row0 + r) * CC + k0 + kq];
        *(float4*)&hs[r + 32][kq] = *(const float4*)&h[(size_t)(row0 + r + 32) * CC + k0 + kq];
        *(float4*)&ws[r][kq]      = *(const float4*)&W[(size_t)(col0 + r) * CC + k0 + kq];
        *(float4*)&ws[r + 32][kq] = *(const float4*)&W[(size_t)(col0 + r + 32) * CC + k0 + kq];
        __syncthreads();
#pragma unroll
        for (int kk = 0; kk < 32; kk++) {
            float hv[4], wv[4];
#pragma unroll
            for (int i = 0; i < 4; i++) hv[i] = hs[ty * 4 + i][kk];
#pragma unroll
            for (int j = 0; j < 4; j++) wv[j] = ws[tx * 4 + j][kk];
#pragma unroll
            for (int i = 0; i < 4; i++)
#pragma unroll
                for (int j = 0; j < 4; j++) acc[i][j] = fmaf(hv[i], wv[j], acc[i][j]);
        }
        __syncthreads();
    }
#pragma unroll
    for (int i = 0; i < 4; i++) {
#pragma unroll
        for (int j = 0; j < 4; j++) {
            const int c = col0 + tx * 4 + j;
            g_Wh[(size_t)(row0 + ty * 4 + i) * CC + c] = acc[i][j] + b[c];
        }
    }
}

// ---------------------------------------------------------------------------
// Kernel 2: src/dst projections. One warp per row.
// ---------------------------------------------------------------------------
__global__ __launch_bounds__(256) void srcdst_kernel(const float* __restrict__ a) {
    const int n = blockIdx.x * 8 + (threadIdx.x >> 5);
    const int l = threadIdx.x & 31;
#pragma unroll
    for (int h = 0; h < HH; h++) {
        float s = 0.f, dd = 0.f;
#pragma unroll
        for (int q = 0; q < 2; q++) {
            const int d = l + q * 32;
            const float w = g_Wh[(size_t)n * CC + h * DD + d];
            s  = fmaf(w, a[h * 128 + d], s);
            dd = fmaf(w, a[h * 128 + 64 + d], dd);
        }
#pragma unroll
        for (int off = 16; off > 0; off >>= 1) {
            s  += __shfl_xor_sync(0xFFFFFFFFu, s, off);
            dd += __shfl_xor_sync(0xFFFFFFFFu, dd, off);
        }
        if (l == 0) { g_src[n * HH + h] = s; g_dst[n * HH + h] = dd; }
    }
}

// ---------------------------------------------------------------------------
// Kernel 3: gdmax[h] = max_n dst[n,h]
// ---------------------------------------------------------------------------
__global__ __launch_bounds__(256) void gdmax_kernel() {
    __shared__ float red[256];
    const int t = threadIdx.x;
    const int h = t & 3;
    float m = -3.4e38f;
    for (int n = t >> 2; n < NN; n += 64) m = fmaxf(m, g_dst[n * HH + h]);
    red[t] = m;
    __syncthreads();
#pragma unroll
    for (int s = 128; s >= 4; s >>= 1) {
        if (t < s) red[t] = fmaxf(red[t], red[t + s]);
        __syncthreads();
    }
    if (t < 4) g_gdmax[t] = red[t];
}

// ---------------------------------------------------------------------------
// Kernel 4: fused attention. TI=32 rows, TJ=64 j-tile, 256 threads.
// m_i = lrelu(src_i + gdmax_h) is a global softmax-max upper bound -> no rescale.
// Stage A thread: (ilA = t&31, hA = (t>>5)&3, jhalf = t>>7); 32 jj each.
//   adj_s[il*65+jj]  -> read banks (il+jj)%32: conflict-free
//   p = adj * exp(lrelu(src+dst) - m)
// Stage B thread: (hh = t>>6, il_g = (t>>4)&3, dg4 = t&15), 8il x 4d microtile
//   packed il-pairs into f32x2 lanes (pairs come free from LDS.128 regs).
//   wh read: warp spans 256B -> 2 wf; p reads: 1 line -> 1 wf each. 4 wf/jj
//   vs 32 FMA-pipe cycles -> FMA-bound.
// ---------------------------------------------------------------------------
__global__ __launch_bounds__(256) void attn_kernel(const int* __restrict__ adj,
                                                   float* __restrict__ out) {
    extern __shared__ float sm[];
    float* wh_s  = sm;                        // 16384 floats
    float* p_s   = sm + 16384;                // 8192  (TJ*4 x 32, [jj*4+h][il])
    float* dst_s = sm + 24576;                // 256
    float* ms    = sm + 24832;                // 128   [il*4+h]
    float* srcs  = sm + 24960;                // 128
    float* lred  = sm + 25088;                // 256
    float* ls    = sm + 25344;                // 128   [il*4+h]
    int*   adj_s = (int*)(sm + 25472);        // 32*65 = 2080 ints
    // total = 27552 floats = 110208 B

    const int t  = threadIdx.x;
    const int i0 = blockIdx.x * TI;

    if (t < 128) {
        const int il = t >> 2, h = t & 3;
        const float s = g_src[(i0 + il) * HH + h];
        srcs[t] = s;
        const float mm = s + g_gdmax[h];
        ms[t] = fmaxf(mm, ALPHA * mm);
    }

    // stage-A identity
    const int ilA = t & 31, hA = (t >> 5) & 3, jhalf = t >> 7;
    // stage-B identity
    const int hh = t >> 6, il_g = (t >> 4) & 3, dg4 = t & 15;

    uint64_t acc[4][4];   // [il-pair][d], each lane-pair = (il0, il1)
#pragma unroll
    for (int i = 0; i < 4; i++)
#pragma unroll
        for (int j = 0; j < 4; j++) acc[i][j] = 0ull;
    float lsum = 0.f;

    __syncthreads();
    const float sA = srcs[ilA * 4 + hA];
    const float mA = ms[ilA * 4 + hA];

    for (int j0 = 0; j0 < NN; j0 += TJ) {
        __syncthreads();  // previous stage A/B consumers done before overwrite
        // Wh tile: 16384 floats, 16 float4 per thread, coalesced
#pragma unroll
        for (int q = 0; q < 16; q++) {
            const int idx = (t + q * 256) * 4;
            *(float4*)&wh_s[idx] = *(const float4*)&g_Wh[(size_t)j0 * CC + idx];
        }
        // dst tile (contiguous 256 floats)
        dst_s[t] = g_dst[j0 * HH + t];
        // adj tile: 32x64 ints; thread loads 8 (2x int4), stores scalar padded
        {
            const int il = t >> 3, jj = (t & 7) * 8;
            const int4 a0 = *(const int4*)&adj[(size_t)(i0 + il) * NN + j0 + jj];
            const int4 a1 = *(const int4*)&adj[(size_t)(i0 + il) * NN + j0 + jj + 4];
            int* dstp = &adj_s[il * 65 + jj];
            dstp[0] = a0.x; dstp[1] = a0.y; dstp[2] = a0.z; dstp[3] = a0.w;
            dstp[4] = a1.x; dstp[5] = a1.y; dstp[6] = a1.z; dstp[7] = a1.w;
        }
        __syncthreads();

        // Stage A: probabilities into p_s[(jj*4+h)*32 + il]
#pragma unroll
        for (int k = 0; k < 32; k++) {
            const int jj = jhalf * 32 + k;
            const float av = (float)adj_s[ilA * 65 + jj];
            float e = sA + dst_s[jj * 4 + hA];
            e = fmaxf(e, ALPHA * e);
            const float p = av * __expf(e - mA);
            p_s[(jj * 4 + hA) * 32 + ilA] = p;
            lsum += p;
        }
        __syncthreads();

        // Stage B: acc += p * wh   (f32x2 packed over il-pairs)
#pragma unroll 4
        for (int jj = 0; jj < TJ; jj++) {
            const float4 w  = *(const float4*)&wh_s[jj * 256 + hh * 64 + dg4 * 4];
            const float4 pa = *(const float4*)&p_s[(jj * 4 + hh) * 32 + il_g * 8];
            const float4 pb = *(const float4*)&p_s[(jj * 4 + hh) * 32 + il_g * 8 + 4];
            const uint64_t P01 = pack2(pa.x, pa.y);
            const uint64_t P23 = pack2(pa.z, pa.w);
            const uint64_t P45 = pack2(pb.x, pb.y);
            const uint64_t P67 = pack2(pb.z, pb.w);
            const uint64_t Wx = dup2(w.x), Wy = dup2(w.y), Wz = dup2(w.z), Ww = dup2(w.w);
            ffma2(acc[0][0], P01, Wx); ffma2(acc[0][1], P01, Wy);
            ffma2(acc[0][2], P01, Wz); ffma2(acc[0][3], P01, Ww);
            ffma2(acc[1][0], P23, Wx); ffma2(acc[1][1], P23, Wy);
            ffma2(acc[1][2], P23, Wz); ffma2(acc[1][3], P23, Ww);
            ffma2(acc[2][0], P45, Wx); ffma2(acc[2][1], P45, Wy);
            ffma2(acc[2][2], P45, Wz); ffma2(acc[2][3], P45, Ww);
            ffma2(acc[3][0], P67, Wx); ffma2(acc[3][1], P67, Wy);
            ffma2(acc[3][2], P67, Wz); ffma2(acc[3][3], P67, Ww);
        }
    }

    // reduce l over the 2 jhalf partials per (il,h)
    __syncthreads();
    lred[t] = lsum;
    __syncthreads();
    if (t < 128) {
        const int il = t & 31, h = t >> 5;
        ls[il * 4 + h] = lred[t] + lred[t + 128];
    }
    __syncthreads();

    // epilogue: normalize + store
#pragma unroll
    for (int rp = 0; rp < 4; rp++) {
        const int il0 = il_g * 8 + rp * 2;
        const float inv0 = 1.0f / ls[il0 * 4 + hh];
        const float inv1 = 1.0f / ls[(il0 + 1) * 4 + hh];
        float4 o0, o1;
        const float2 v0 = unpack2(acc[rp][0]);
        const float2 v1 = unpack2(acc[rp][1]);
        const float2 v2 = unpack2(acc[rp][2]);
        const float2 v3 = unpack2(acc[rp][3]);
        o0.x = v0.x * inv0; o0.y = v1.x * inv0; o0.z = v2.x * inv0; o0.w = v3.x * inv0;
        o1.x = v0.y * inv1; o1.y = v1.y * inv1; o1.z = v2.y * inv1; o1.w = v3.y * inv1;
        *(float4*)&out[(size_t)(i0 + il0) * CC + hh * 64 + dg4 * 4] = o0;
        *(float4*)&out[(size_t)(i0 + il0 + 1) * CC + hh * 64 + dg4 * 4] = o1;
    }
}

// ---------------------------------------------------------------------------
extern "C" void kernel_launch(void* const* d_in, const int* in_sizes, int n_in,
                              void* d_out, int out_size) {
    const float* h   = (const float*)d_in[0];
    const int*   adj = (const int*)d_in[1];
    const float* W   = (const float*)d_in[2];
    const float* b   = (const float*)d_in[3];
    const float* a   = (const float*)d_in[4];
    float* out = (float*)d_out;

    const int attn_smem = 27552 * (int)sizeof(float);  // ~107.6KB
    cudaFuncSetAttribute(attn_kernel, cudaFuncAttributeMaxDynamicSharedMemorySize, attn_smem);

    gemm_kernel<<<dim3(NN / 64, CC / 64), 256>>>(h, W, b);
    srcdst_kernel<<<NN / 8, 256>>>(a);
    gdmax_kernel<<<1, 256>>>();
    attn_kernel<<<NN / TI, 256, attn_smem>>>(adj, out);
}

// round 3
// speedup vs baseline: 1.0832x; 1.0013x over previous
#include <cuda_runtime.h>
#include <cuda_bf16.h>
#include <cstdint>

#define NN 4096
#define CC 256      // IN_DIM = OUT_DIM = 256
#define HH 4
#define DD 64
#define ALPHA 0.2f
#define TI 32
#define TJ 64

// Scratch (device globals: no allocation allowed)
__device__ float g_Wh[NN * CC];
__device__ float g_src[NN * HH];
__device__ float g_dst[NN * HH];
__device__ float g_gdmax[HH];

// ---------------------------------------------------------------------------
// f32x2 packed-math helpers (sm_103a)
// ---------------------------------------------------------------------------
__device__ __forceinline__ uint64_t pack2(float lo, float hi) {
    uint64_t r; asm("mov.b64 %0, {%1,%2};" : "=l"(r) : "f"(lo), "f"(hi)); return r;
}
__device__ __forceinline__ uint64_t dup2(float v) {
    uint64_t r; asm("mov.b64 %0, {%1,%1};" : "=l"(r) : "f"(v)); return r;
}
__device__ __forceinline__ void ffma2(uint64_t& d, uint64_t a, uint64_t b) {
    asm("fma.rn.f32x2 %0, %1, %2, %0;" : "+l"(d) : "l"(a), "l"(b));
}
__device__ __forceinline__ float2 unpack2(uint64_t v) {
    float2 f; asm("mov.b64 {%0,%1}, %2;" : "=f"(f.x), "=f"(f.y) : "l"(v)); return f;
}

// ---------------------------------------------------------------------------
// Kernel 1: Wh = h @ W^T + b
// ---------------------------------------------------------------------------
__global__ __launch_bounds__(256) void gemm_kernel(const float* __restrict__ h,
                                                   const float* __restrict__ W,
                                                   const float* __restrict__ b) {
    __shared__ float hs[64][36];
    __shared__ float ws[64][36];
    const int row0 = blockIdx.x * 64;
    const int col0 = blockIdx.y * 64;
    const int t = threadIdx.x;
    const int tx = t & 15, ty = t >> 4;

    float acc[4][4];
#pragma unroll
    for (int i = 0; i < 4; i++)
#pragma unroll
        for (int j = 0; j < 4; j++) acc[i][j] = 0.f;

    for (int k0 = 0; k0 < CC; k0 += 32) {
        const int r = t >> 3, kq = (t & 7) * 4;
        *(float4*)&hs[r][kq]      = *(const float4*)&h[(size_t)(row0 + r) * CC + k0 + kq];
        *(float4*)&hs[r + 32][kq] = *(const float4*)&h[(size_t)(row0 + r + 32) * CC + k0 + kq];
        *(float4*)&ws[r][kq]      = *(const float4*)&W[(size_t)(col0 + r) * CC + k0 + kq];
        *(float4*)&ws[r + 32][kq] = *(const float4*)&W[(size_t)(col0 + r + 32) * CC + k0 + kq];
        __syncthreads();
#pragma unroll
        for (int kk = 0; kk < 32; kk++) {
            float hv[4], wv[4];
#pragma unroll
            for (int i = 0; i < 4; i++) hv[i] = hs[ty * 4 + i][kk];
#pragma unroll
            for (int j = 0; j < 4; j++) wv[j] = ws[tx * 4 + j][kk];
#pragma unroll
            for (int i = 0; i < 4; i++)
#pragma unroll
                for (int j = 0; j < 4; j++) acc[i][j] = fmaf(hv[i], wv[j], acc[i][j]);
        }
        __syncthreads();
    }
#pragma unroll
    for (int i = 0; i < 4; i++) {
#pragma unroll
        for (int j = 0; j < 4; j++) {
            const int c = col0 + tx * 4 + j;
            g_Wh[(size_t)(row0 + ty * 4 + i) * CC + c] = acc[i][j] + b[c];
        }
    }
}

// ---------------------------------------------------------------------------
// Kernel 2: src/dst projections. One warp per row.
// ---------------------------------------------------------------------------
__global__ __launch_bounds__(256) void srcdst_kernel(const float* __restrict__ a) {
    const int n = blockIdx.x * 8 + (threadIdx.x >> 5);
    const int l = threadIdx.x & 31;
#pragma unroll
    for (int h = 0; h < HH; h++) {
        float s = 0.f, dd = 0.f;
#pragma unroll
        for (int q = 0; q < 2; q++) {
            const int d = l + q * 32;
            const float w = g_Wh[(size_t)n * CC + h * DD + d];
            s  = fmaf(w, a[h * 128 + d], s);
            dd = fmaf(w, a[h * 128 + 64 + d], dd);
        }
#pragma unroll
        for (int off = 16; off > 0; off >>= 1) {
            s  += __shfl_xor_sync(0xFFFFFFFFu, s, off);
            dd += __shfl_xor_sync(0xFFFFFFFFu, dd, off);
        }
        if (l == 0) { g_src[n * HH + h] = s; g_dst[n * HH + h] = dd; }
    }
}

// ---------------------------------------------------------------------------
// Kernel 3: gdmax[h] = max_n dst[n,h]
// ---------------------------------------------------------------------------
__global__ __launch_bounds__(256) void gdmax_kernel() {
    __shared__ float red[256];
    const int t = threadIdx.x;
    const int h = t & 3;
    float m = -3.4e38f;
    for (int n = t >> 2; n < NN; n += 64) m = fmaxf(m, g_dst[n * HH + h]);
    red[t] = m;
    __syncthreads();
#pragma unroll
    for (int s = 128; s >= 4; s >>= 1) {
        if (t < s) red[t] = fmaxf(red[t], red[t + s]);
        __syncthreads();
    }
    if (t < 4) g_gdmax[t] = red[t];
}

// ---------------------------------------------------------------------------
// Kernel 4: fused attention. TI=32 rows, TJ=64 j-tile, 256 threads.
// m_i = lrelu(src_i + gdmax_h) is a global softmax-max upper bound -> no rescale.
// Stage A thread: (ilA = t&31, hA = (t>>5)&3, jhalf = t>>7); 32 jj each.
//   adj_s[il*65+jj]  -> read banks (il+jj)%32: conflict-free
//   p = adj * exp(lrelu(src+dst) - m)
// Stage B thread: (hh = t>>6, il_g = (t>>4)&3, dg4 = t&15), 8il x 4d microtile
//   packed il-pairs into f32x2 lanes (pairs come free from LDS.128 regs).
//   wh read: warp spans 256B -> 2 wf; p reads: 1 line -> 1 wf each. 4 wf/jj
//   vs 32 FMA-pipe cycles -> FMA-bound.
// ---------------------------------------------------------------------------
__global__ __launch_bounds__(256) void attn_kernel(const int* __restrict__ adj,
                                                   float* __restrict__ out) {
    extern __shared__ float sm[];
    float* wh_s  = sm;                        // 16384 floats
    float* p_s   = sm + 16384;                // 8192  (TJ*4 x 32, [jj*4+h][il])
    float* dst_s = sm + 24576;                // 256
    float* ms    = sm + 24832;                // 128   [il*4+h]
    float* srcs  = sm + 24960;                // 128
    float* lred  = sm + 25088;                // 256
    float* ls    = sm + 25344;                // 128   [il*4+h]
    int*   adj_s = (int*)(sm + 25472);        // 32*65 = 2080 ints
    // total = 27552 floats = 110208 B

    const int t  = threadIdx.x;
    const int i0 = blockIdx.x * TI;

    if (t < 128) {
        const int il = t >> 2, h = t & 3;
        const float s = g_src[(i0 + il) * HH + h];
        srcs[t] = s;
        const float mm = s + g_gdmax[h];
        ms[t] = fmaxf(mm, ALPHA * mm);
    }

    // stage-A identity
    const int ilA = t & 31, hA = (t >> 5) & 3, jhalf = t >> 7;
    // stage-B identity
    const int hh = t >> 6, il_g = (t >> 4) & 3, dg4 = t & 15;

    uint64_t acc[4][4];   // [il-pair][d], each lane-pair = (il0, il1)
#pragma unroll
    for (int i = 0; i < 4; i++)
#pragma unroll
        for (int j = 0; j < 4; j++) acc[i][j] = 0ull;
    float lsum = 0.f;

    __syncthreads();
    const float sA = srcs[ilA * 4 + hA];
    const float mA = ms[ilA * 4 + hA];

    for (int j0 = 0; j0 < NN; j0 += TJ) {
        __syncthreads();  // previous stage A/B consumers done before overwrite
        // Wh tile: 16384 floats, 16 float4 per thread, coalesced
#pragma unroll
        for (int q = 0; q < 16; q++) {
            const int idx = (t + q * 256) * 4;
            *(float4*)&wh_s[idx] = *(const float4*)&g_Wh[(size_t)j0 * CC + idx];
        }
        // dst tile (contiguous 256 floats)
        dst_s[t] = g_dst[j0 * HH + t];
        // adj tile: 32x64 ints; thread loads 8 (2x int4), stores scalar padded
        {
            const int il = t >> 3, jj = (t & 7) * 8;
            const int4 a0 = *(const int4*)&adj[(size_t)(i0 + il) * NN + j0 + jj];
            const int4 a1 = *(const int4*)&adj[(size_t)(i0 + il) * NN + j0 + jj + 4];
            int* dstp = &adj_s[il * 65 + jj];
            dstp[0] = a0.x; dstp[1] = a0.y; dstp[2] = a0.z; dstp[3] = a0.w;
            dstp[4] = a1.x; dstp[5] = a1.y; dstp[6] = a1.z; dstp[7] = a1.w;
        }
        __syncthreads();

        // Stage A: probabilities into p_s[(jj*4+h)*32 + il]
#pragma unroll
        for (int k = 0; k < 32; k++) {
            const int jj = jhalf * 32 + k;
            const float av = (float)adj_s[ilA * 65 + jj];
            float e = sA + dst_s[jj * 4 + hA];
            e = fmaxf(e, ALPHA * e);
            const float p = av * __expf(e - mA);
            p_s[(jj * 4 + hA) * 32 + ilA] = p;
            lsum += p;
        }
        __syncthreads();

        // Stage B: acc += p * wh   (f32x2 packed over il-pairs)
#pragma unroll 4
        for (int jj = 0; jj < TJ; jj++) {
            const float4 w  = *(const float4*)&wh_s[jj * 256 + hh * 64 + dg4 * 4];
            const float4 pa = *(const float4*)&p_s[(jj * 4 + hh) * 32 + il_g * 8];
            const float4 pb = *(const float4*)&p_s[(jj * 4 + hh) * 32 + il_g * 8 + 4];
            const uint64_t P01 = pack2(pa.x, pa.y);
            const uint64_t P23 = pack2(pa.z, pa.w);
            const uint64_t P45 = pack2(pb.x, pb.y);
            const uint64_t P67 = pack2(pb.z, pb.w);
            const uint64_t Wx = dup2(w.x), Wy = dup2(w.y), Wz = dup2(w.z), Ww = dup2(w.w);
            ffma2(acc[0][0], P01, Wx); ffma2(acc[0][1], P01, Wy);
            ffma2(acc[0][2], P01, Wz); ffma2(acc[0][3], P01, Ww);
            ffma2(acc[1][0], P23, Wx); ffma2(acc[1][1], P23, Wy);
            ffma2(acc[1][2], P23, Wz); ffma2(acc[1][3], P23, Ww);
            ffma2(acc[2][0], P45, Wx); ffma2(acc[2][1], P45, Wy);
            ffma2(acc[2][2], P45, Wz); ffma2(acc[2][3], P45, Ww);
            ffma2(acc[3][0], P67, Wx); ffma2(acc[3][1], P67, Wy);
            ffma2(acc[3][2], P67, Wz); ffma2(acc[3][3], P67, Ww);
        }
    }

    // reduce l over the 2 jhalf partials per (il,h)
    __syncthreads();
    lred[t] = lsum;
    __syncthreads();
    if (t < 128) {
        const int il = t & 31, h = t >> 5;
        ls[il * 4 + h] = lred[t] + lred[t + 128];
    }
    __syncthreads();

    // epilogue: normalize + store
#pragma unroll
    for (int rp = 0; rp < 4; rp++) {
        const int il0 = il_g * 8 + rp * 2;
        const float inv0 = 1.0f / ls[il0 * 4 + hh];
        const float inv1 = 1.0f / ls[(il0 + 1) * 4 + hh];
        float4 o0, o1;
        const float2 v0 = unpack2(acc[rp][0]);
        const float2 v1 = unpack2(acc[rp][1]);
        const float2 v2 = unpack2(acc[rp][2]);
        const float2 v3 = unpack2(acc[rp][3]);
        o0.x = v0.x * inv0; o0.y = v1.x * inv0; o0.z = v2.x * inv0; o0.w = v3.x * inv0;
        o1.x = v0.y * inv1; o1.y = v1.y * inv1; o1.z = v2.y * inv1; o1.w = v3.y * inv1;
        *(float4*)&out[(size_t)(i0 + il0) * CC + hh * 64 + dg4 * 4] = o0;
        *(float4*)&out[(size_t)(i0 + il0 + 1) * CC + hh * 64 + dg4 * 4] = o1;
    }
}

// ---------------------------------------------------------------------------
extern "C" void kernel_launch(void* const* d_in, const int* in_sizes, int n_in,
                              void* d_out, int out_size) {
    const float* h   = (const float*)d_in[0];
    const int*   adj = (const int*)d_in[1];
    const float* W   = (const float*)d_in[2];
    const float* b   = (const float*)d_in[3];
    const float* a   = (const float*)d_in[4];
    float* out = (float*)d_out;

    const int attn_smem = 27552 * (int)sizeof(float);  // ~107.6KB
    cudaFuncSetAttribute(attn_kernel, cudaFuncAttributeMaxDynamicSharedMemorySize, attn_smem);

    gemm_kernel<<<dim3(NN / 64, CC / 64), 256>>>(h, W, b);
    srcdst_kernel<<<NN / 8, 256>>>(a);
    gdmax_kernel<<<1, 256>>>();
    attn_kernel<<<NN / TI, 256, attn_smem>>>(adj, out);
}

// round 4
// speedup vs baseline: 1.0838x; 1.0006x over previous
#include <cuda_runtime.h>
#include <cuda_bf16.h>
#include <cstdint>

#define NN 4096
#define CC 256      // IN_DIM = OUT_DIM = 256
#define HH 4
#define DD 64
#define ALPHA 0.2f
#define TI 32
#define TJ 64

// Scratch (device globals: no allocation allowed)
__device__ float g_Wh[NN * CC];
__device__ float g_src[NN * HH];
__device__ float g_dst[NN * HH];
__device__ float g_gdmax[HH];

// ---------------------------------------------------------------------------
// f32x2 packed-math helpers (sm_103a)
// ---------------------------------------------------------------------------
__device__ __forceinline__ uint64_t pack2(float lo, float hi) {
    uint64_t r; asm("mov.b64 %0, {%1,%2};" : "=l"(r) : "f"(lo), "f"(hi)); return r;
}
__device__ __forceinline__ uint64_t dup2(float v) {
    uint64_t r; asm("mov.b64 %0, {%1,%1};" : "=l"(r) : "f"(v)); return r;
}
__device__ __forceinline__ void ffma2(uint64_t& d, uint64_t a, uint64_t b) {
    asm("fma.rn.f32x2 %0, %1, %2, %0;" : "+l"(d) : "l"(a), "l"(b));
}
__device__ __forceinline__ float2 unpack2(uint64_t v) {
    float2 f; asm("mov.b64 {%0,%1}, %2;" : "=f"(f.x), "=f"(f.y) : "l"(v)); return f;
}

// ---------------------------------------------------------------------------
// Kernel 1: Wh = h @ W^T + b
// ---------------------------------------------------------------------------
__global__ __launch_bounds__(256) void gemm_kernel(const float* __restrict__ h,
                                                   const float* __restrict__ W,
                                                   const float* __restrict__ b) {
    __shared__ float hs[64][36];
    __shared__ float ws[64][36];
    const int row0 = blockIdx.x * 64;
    const int col0 = blockIdx.y * 64;
    const int t = threadIdx.x;
    const int tx = t & 15, ty = t >> 4;

    float acc[4][4];
#pragma unroll
    for (int i = 0; i < 4; i++)
#pragma unroll
        for (int j = 0; j < 4; j++) acc[i][j] = 0.f;

    for (int k0 = 0; k0 < CC; k0 += 32) {
        const int r = t >> 3, kq = (t & 7) * 4;
        *(float4*)&hs[r][kq]      = *(const float4*)&h[(size_t)(row0 + r) * CC + k0 + kq];
        *(float4*)&hs[r + 32][kq] = *(const float4*)&h[(size_t)(row0 + r + 32) * CC + k0 + kq];
        *(float4*)&ws[r][kq]      = *(const float4*)&W[(size_t)(col0 + r) * CC + k0 + kq];
        *(float4*)&ws[r + 32][kq] = *(const float4*)&W[(size_t)(col0 + r + 32) * CC + k0 + kq];
        __syncthreads();
#pragma unroll
        for (int kk = 0; kk < 32; kk++) {
            float hv[4], wv[4];
#pragma unroll
            for (int i = 0; i < 4; i++) hv[i] = hs[ty * 4 + i][kk];
#pragma unroll
            for (int j = 0; j < 4; j++) wv[j] = ws[tx * 4 + j][kk];
#pragma unroll
            for (int i = 0; i < 4; i++)
#pragma unroll
                for (int j = 0; j < 4; j++) acc[i][j] = fmaf(hv[i], wv[j], acc[i][j]);
        }
        __syncthreads();
    }
#pragma unroll
    for (int i = 0; i < 4; i++) {
#pragma unroll
        for (int j = 0; j < 4; j++) {
            const int c = col0 + tx * 4 + j;
            g_Wh[(size_t)(row0 + ty * 4 + i) * CC + c] = acc[i][j] + b[c];
        }
    }
}

// ---------------------------------------------------------------------------
// Kernel 2: src/dst projections. One warp per row.
// ---------------------------------------------------------------------------
__global__ __launch_bounds__(256) void srcdst_kernel(const float* __restrict__ a) {
    const int n = blockIdx.x * 8 + (threadIdx.x >> 5);
    const int l = threadIdx.x & 31;
#pragma unroll
    for (int h = 0; h < HH; h++) {
        float s = 0.f, dd = 0.f;
#pragma unroll
        for (int q = 0; q < 2; q++) {
            const int d = l + q * 32;
            const float w = g_Wh[(size_t)n * CC + h * DD + d];
            s  = fmaf(w, a[h * 128 + d], s);
            dd = fmaf(w, a[h * 128 + 64 + d], dd);
        }
#pragma unroll
        for (int off = 16; off > 0; off >>= 1) {
            s  += __shfl_xor_sync(0xFFFFFFFFu, s, off);
            dd += __shfl_xor_sync(0xFFFFFFFFu, dd, off);
        }
        if (l == 0) { g_src[n * HH + h] = s; g_dst[n * HH + h] = dd; }
    }
}

// ---------------------------------------------------------------------------
// Kernel 3: gdmax[h] = max_n dst[n,h]
// ---------------------------------------------------------------------------
__global__ __launch_bounds__(256) void gdmax_kernel() {
    __shared__ float red[256];
    const int t = threadIdx.x;
    const int h = t & 3;
    float m = -3.4e38f;
    for (int n = t >> 2; n < NN; n += 64) m = fmaxf(m, g_dst[n * HH + h]);
    red[t] = m;
    __syncthreads();
#pragma unroll
    for (int s = 128; s >= 4; s >>= 1) {
        if (t < s) red[t] = fmaxf(red[t], red[t + s]);
        __syncthreads();
    }
    if (t < 4) g_gdmax[t] = red[t];
}

// ---------------------------------------------------------------------------
// Kernel 4: fused attention. TI=32 rows, TJ=64 j-tile, 256 threads.
// m_i = lrelu(src_i + gdmax_h) is a global softmax-max upper bound -> no rescale.
// Stage A thread: (ilA = t&31, hA = (t>>5)&3, jhalf = t>>7); 32 jj each.
//   adj_s[il*65+jj]  -> read banks (il+jj)%32: conflict-free
//   p = adj * exp(lrelu(src+dst) - m)
// Stage B thread: (hh = t>>6, il_g = (t>>4)&3, dg4 = t&15), 8il x 4d microtile
//   packed il-pairs into f32x2 lanes (pairs come free from LDS.128 regs).
//   wh read: warp spans 256B -> 2 wf; p reads: 1 line -> 1 wf each. 4 wf/jj
//   vs 32 FMA-pipe cycles -> FMA-bound.
// ---------------------------------------------------------------------------
__global__ __launch_bounds__(256) void attn_kernel(const int* __restrict__ adj,
                                                   float* __restrict__ out) {
    extern __shared__ float sm[];
    float* wh_s  = sm;                        // 16384 floats
    float* p_s   = sm + 16384;                // 8192  (TJ*4 x 32, [jj*4+h][il])
    float* dst_s = sm + 24576;                // 256
    float* ms    = sm + 24832;                // 128   [il*4+h]
    float* srcs  = sm + 24960;                // 128
    float* lred  = sm + 25088;                // 256
    float* ls    = sm + 25344;                // 128   [il*4+h]
    int*   adj_s = (int*)(sm + 25472);        // 32*65 = 2080 ints
    // total = 27552 floats = 110208 B

    const int t  = threadIdx.x;
    const int i0 = blockIdx.x * TI;

    if (t < 128) {
        const int il = t >> 2, h = t & 3;
        const float s = g_src[(i0 + il) * HH + h];
        srcs[t] = s;
        const float mm = s + g_gdmax[h];
        ms[t] = fmaxf(mm, ALPHA * mm);
    }

    // stage-A identity
    const int ilA = t & 31, hA = (t >> 5) & 3, jhalf = t >> 7;
    // stage-B identity
    const int hh = t >> 6, il_g = (t >> 4) & 3, dg4 = t & 15;

    uint64_t acc[4][4];   // [il-pair][d], each lane-pair = (il0, il1)
#pragma unroll
    for (int i = 0; i < 4; i++)
#pragma unroll
        for (int j = 0; j < 4; j++) acc[i][j] = 0ull;
    float lsum = 0.f;

    __syncthreads();
    const float sA = srcs[ilA * 4 + hA];
    const float mA = ms[ilA * 4 + hA];

    for (int j0 = 0; j0 < NN; j0 += TJ) {
        __syncthreads();  // previous stage A/B consumers done before overwrite
        // Wh tile: 16384 floats, 16 float4 per thread, coalesced
#pragma unroll
        for (int q = 0; q < 16; q++) {
            const int idx = (t + q * 256) * 4;
            *(float4*)&wh_s[idx] = *(const float4*)&g_Wh[(size_t)j0 * CC + idx];
        }
        // dst tile (contiguous 256 floats)
        dst_s[t] = g_dst[j0 * HH + t];
        // adj tile: 32x64 ints; thread loads 8 (2x int4), stores scalar padded
        {
            const int il = t >> 3, jj = (t & 7) * 8;
            const int4 a0 = *(const int4*)&adj[(size_t)(i0 + il) * NN + j0 + jj];
            const int4 a1 = *(const int4*)&adj[(size_t)(i0 + il) * NN + j0 + jj + 4];
            int* dstp = &adj_s[il * 65 + jj];
            dstp[0] = a0.x; dstp[1] = a0.y; dstp[2] = a0.z; dstp[3] = a0.w;
            dstp[4] = a1.x; dstp[5] = a1.y; dstp[6] = a1.z; dstp[7] = a1.w;
        }
        __syncthreads();

        // Stage A: probabilities into p_s[(jj*4+h)*32 + il]
#pragma unroll
        for (int k = 0; k < 32; k++) {
            const int jj = jhalf * 32 + k;
            const float av = (float)adj_s[ilA * 65 + jj];
            float e = sA + dst_s[jj * 4 + hA];
            e = fmaxf(e, ALPHA * e);
            const float p = av * __expf(e - mA);
            p_s[(jj * 4 + hA) * 32 + ilA] = p;
            lsum += p;
        }
        __syncthreads();

        // Stage B: acc += p * wh   (f32x2 packed over il-pairs)
#pragma unroll 4
        for (int jj = 0; jj < TJ; jj++) {
            const float4 w  = *(const float4*)&wh_s[jj * 256 + hh * 64 + dg4 * 4];
            const float4 pa = *(const float4*)&p_s[(jj * 4 + hh) * 32 + il_g * 8];
            const float4 pb = *(const float4*)&p_s[(jj * 4 + hh) * 32 + il_g * 8 + 4];
            const uint64_t P01 = pack2(pa.x, pa.y);
            const uint64_t P23 = pack2(pa.z, pa.w);
            const uint64_t P45 = pack2(pb.x, pb.y);
            const uint64_t P67 = pack2(pb.z, pb.w);
            const uint64_t Wx = dup2(w.x), Wy = dup2(w.y), Wz = dup2(w.z), Ww = dup2(w.w);
            ffma2(acc[0][0], P01, Wx); ffma2(acc[0][1], P01, Wy);
            ffma2(acc[0][2], P01, Wz); ffma2(acc[0][3], P01, Ww);
            ffma2(acc[1][0], P23, Wx); ffma2(acc[1][1], P23, Wy);
            ffma2(acc[1][2], P23, Wz); ffma2(acc[1][3], P23, Ww);
            ffma2(acc[2][0], P45, Wx); ffma2(acc[2][1], P45, Wy);
            ffma2(acc[2][2], P45, Wz); ffma2(acc[2][3], P45, Ww);
            ffma2(acc[3][0], P67, Wx); ffma2(acc[3][1], P67, Wy);
            ffma2(acc[3][2], P67, Wz); ffma2(acc[3][3], P67, Ww);
        }
    }

    // reduce l over the 2 jhalf partials per (il,h)
    __syncthreads();
    lred[t] = lsum;
    __syncthreads();
    if (t < 128) {
        const int il = t & 31, h = t >> 5;
        ls[il * 4 + h] = lred[t] + lred[t + 128];
    }
    __syncthreads();

    // epilogue: normalize + store
#pragma unroll
    for (int rp = 0; rp < 4; rp++) {
        const int il0 = il_g * 8 + rp * 2;
        const float inv0 = 1.0f / ls[il0 * 4 + hh];
        const float inv1 = 1.0f / ls[(il0 + 1) * 4 + hh];
        float4 o0, o1;
        const float2 v0 = unpack2(acc[rp][0]);
        const float2 v1 = unpack2(acc[rp][1]);
        const float2 v2 = unpack2(acc[rp][2]);
        const float2 v3 = unpack2(acc[rp][3]);
        o0.x = v0.x * inv0; o0.y = v1.x * inv0; o0.z = v2.x * inv0; o0.w = v3.x * inv0;
        o1.x = v0.y * inv1; o1.y = v1.y * inv1; o1.z = v2.y * inv1; o1.w = v3.y * inv1;
        *(float4*)&out[(size_t)(i0 + il0) * CC + hh * 64 + dg4 * 4] = o0;
        *(float4*)&out[(size_t)(i0 + il0 + 1) * CC + hh * 64 + dg4 * 4] = o1;
    }
}

// ---------------------------------------------------------------------------
extern "C" void kernel_launch(void* const* d_in, const int* in_sizes, int n_in,
                              void* d_out, int out_size) {
    const float* h   = (const float*)d_in[0];
    const int*   adj = (const int*)d_in[1];
    const float* W   = (const float*)d_in[2];
    const float* b   = (const float*)d_in[3];
    const float* a   = (const float*)d_in[4];
    float* out = (float*)d_out;

    const int attn_smem = 27552 * (int)sizeof(float);  // ~107.6KB
    cudaFuncSetAttribute(attn_kernel, cudaFuncAttributeMaxDynamicSharedMemorySize, attn_smem);

    gemm_kernel<<<dim3(NN / 64, CC / 64), 256>>>(h, W, b);
    srcdst_kernel<<<NN / 8, 256>>>(a);
    gdmax_kernel<<<1, 256>>>();
    attn_kernel<<<NN / TI, 256, attn_smem>>>(adj, out);
}

// round 5
// speedup vs baseline: 1.0896x; 1.0053x over previous
#include <cuda_runtime.h>
#include <cuda_bf16.h>
#include <cstdint>

#define NN 4096
#define CC 256      // IN_DIM = OUT_DIM = 256
#define HH 4
#define DD 64
#define ALPHA 0.2f
#define TI 32
#define TJ 64

// Scratch (device globals: no allocation allowed)
__device__ float g_Wh[NN * CC];
__device__ float g_src[NN * HH];
__device__ float g_dst[NN * HH];
__device__ float g_gdmax[HH];

// ---------------------------------------------------------------------------
// f32x2 packed-math helpers (sm_103a)
// ---------------------------------------------------------------------------
__device__ __forceinline__ uint64_t pack2(float lo, float hi) {
    uint64_t r; asm("mov.b64 %0, {%1,%2};" : "=l"(r) : "f"(lo), "f"(hi)); return r;
}
__device__ __forceinline__ uint64_t dup2(float v) {
    uint64_t r; asm("mov.b64 %0, {%1,%1};" : "=l"(r) : "f"(v)); return r;
}
__device__ __forceinline__ void ffma2(uint64_t& d, uint64_t a, uint64_t b) {
    asm("fma.rn.f32x2 %0, %1, %2, %0;" : "+l"(d) : "l"(a), "l"(b));
}
__device__ __forceinline__ float2 unpack2(uint64_t v) {
    float2 f; asm("mov.b64 {%0,%1}, %2;" : "=f"(f.x), "=f"(f.y) : "l"(v)); return f;
}

// ---------------------------------------------------------------------------
// Kernel 1: Wh = h @ W^T + b
// ---------------------------------------------------------------------------
__global__ __launch_bounds__(256) void gemm_kernel(const float* __restrict__ h,
                                                   const float* __restrict__ W,
                                                   const float* __restrict__ b) {
    __shared__ float hs[64][36];
    __shared__ float ws[64][36];
    const int row0 = blockIdx.x * 64;
    const int col0 = blockIdx.y * 64;
    const int t = threadIdx.x;
    const int tx = t & 15, ty = t >> 4;

    float acc[4][4];
#pragma unroll
    for (int i = 0; i < 4; i++)
#pragma unroll
        for (int j = 0; j < 4; j++) acc[i][j] = 0.f;

    for (int k0 = 0; k0 < CC; k0 += 32) {
        const int r = t >> 3, kq = (t & 7) * 4;
        *(float4*)&hs[r][kq]      = *(const float4*)&h[(size_t)(row0 + r) * CC + k0 + kq];
        *(float4*)&hs[r + 32][kq] = *(const float4*)&h[(size_t)(row0 + r + 32) * CC + k0 + kq];
        *(float4*)&ws[r][kq]      = *(const float4*)&W[(size_t)(col0 + r) * CC + k0 + kq];
        *(float4*)&ws[r + 32][kq] = *(const float4*)&W[(size_t)(col0 + r + 32) * CC + k0 + kq];
        __syncthreads();
#pragma unroll
        for (int kk = 0; kk < 32; kk++) {
            float hv[4], wv[4];
#pragma unroll
            for (int i = 0; i < 4; i++) hv[i] = hs[ty * 4 + i][kk];
#pragma unroll
            for (int j = 0; j < 4; j++) wv[j] = ws[tx * 4 + j][kk];
#pragma unroll
            for (int i = 0; i < 4; i++)
#pragma unroll
                for (int j = 0; j < 4; j++) acc[i][j] = fmaf(hv[i], wv[j], acc[i][j]);
        }
        __syncthreads();
    }
#pragma unroll
    for (int i = 0; i < 4; i++) {
#pragma unroll
        for (int j = 0; j < 4; j++) {
            const int c = col0 + tx * 4 + j;
            g_Wh[(size_t)(row0 + ty * 4 + i) * CC + c] = acc[i][j] + b[c];
        }
    }
}

// ---------------------------------------------------------------------------
// Kernel 2: src/dst projections. One warp per row.
// ---------------------------------------------------------------------------
__global__ __launch_bounds__(256) void srcdst_kernel(const float* __restrict__ a) {
    const int n = blockIdx.x * 8 + (threadIdx.x >> 5);
    const int l = threadIdx.x & 31;
#pragma unroll
    for (int h = 0; h < HH; h++) {
        float s = 0.f, dd = 0.f;
#pragma unroll
        for (int q = 0; q < 2; q++) {
            const int d = l + q * 32;
            const float w = g_Wh[(size_t)n * CC + h * DD + d];
            s  = fmaf(w, a[h * 128 + d], s);
            dd = fmaf(w, a[h * 128 + 64 + d], dd);
        }
#pragma unroll
        for (int off = 16; off > 0; off >>= 1) {
            s  += __shfl_xor_sync(0xFFFFFFFFu, s, off);
            dd += __shfl_xor_sync(0xFFFFFFFFu, dd, off);
        }
        if (l == 0) { g_src[n * HH + h] = s; g_dst[n * HH + h] = dd; }
    }
}

// ---------------------------------------------------------------------------
// Kernel 3: gdmax[h] = max_n dst[n,h]
// ---------------------------------------------------------------------------
__global__ __launch_bounds__(256) void gdmax_kernel() {
    __shared__ float red[256];
    const int t = threadIdx.x;
    const int h = t & 3;
    float m = -3.4e38f;
    for (int n = t >> 2; n < NN; n += 64) m = fmaxf(m, g_dst[n * HH + h]);
    red[t] = m;
    __syncthreads();
#pragma unroll
    for (int s = 128; s >= 4; s >>= 1) {
        if (t < s) red[t] = fmaxf(red[t], red[t + s]);
        __syncthreads();
    }
    if (t < 4) g_gdmax[t] = red[t];
}

// ---------------------------------------------------------------------------
// Kernel 4: fused attention. TI=32 rows, TJ=64 j-tile, 256 threads.
// m_i = lrelu(src_i + gdmax_h) is a global softmax-max upper bound -> no rescale.
// Stage A thread: (ilA = t&31, hA = (t>>5)&3, jhalf = t>>7); 32 jj each.
//   adj_s[il*65+jj]  -> read banks (il+jj)%32: conflict-free
//   p = adj * exp(lrelu(src+dst) - m)
// Stage B thread: (hh = t>>6, il_g = (t>>4)&3, dg4 = t&15), 8il x 4d microtile
//   packed il-pairs into f32x2 lanes (pairs come free from LDS.128 regs).
//   wh read: warp spans 256B -> 2 wf; p reads: 1 line -> 1 wf each. 4 wf/jj
//   vs 32 FMA-pipe cycles -> FMA-bound.
// ---------------------------------------------------------------------------
__global__ __launch_bounds__(256) void attn_kernel(const int* __restrict__ adj,
                                                   float* __restrict__ out) {
    extern __shared__ float sm[];
    float* wh_s  = sm;                        // 16384 floats
    float* p_s   = sm + 16384;                // 8192  (TJ*4 x 32, [jj*4+h][il])
    float* dst_s = sm + 24576;                // 256
    float* ms    = sm + 24832;                // 128   [il*4+h]
    float* srcs  = sm + 24960;                // 128
    float* lred  = sm + 25088;                // 256
    float* ls    = sm + 25344;                // 128   [il*4+h]
    int*   adj_s = (int*)(sm + 25472);        // 32*65 = 2080 ints
    // total = 27552 floats = 110208 B

    const int t  = threadIdx.x;
    const int i0 = blockIdx.x * TI;

    if (t < 128) {
        const int il = t >> 2, h = t & 3;
        const float s = g_src[(i0 + il) * HH + h];
        srcs[t] = s;
        const float mm = s + g_gdmax[h];
        ms[t] = fmaxf(mm, ALPHA * mm);
    }

    // stage-A identity
    const int ilA = t & 31, hA = (t >> 5) & 3, jhalf = t >> 7;
    // stage-B identity
    const int hh = t >> 6, il_g = (t >> 4) & 3, dg4 = t & 15;

    uint64_t acc[4][4];   // [il-pair][d], each lane-pair = (il0, il1)
#pragma unroll
    for (int i = 0; i < 4; i++)
#pragma unroll
        for (int j = 0; j < 4; j++) acc[i][j] = 0ull;
    float lsum = 0.f;

    __syncthreads();
    const float sA = srcs[ilA * 4 + hA];
    const float mA = ms[ilA * 4 + hA];

    for (int j0 = 0; j0 < NN; j0 += TJ) {
        __syncthreads();  // previous stage A/B consumers done before overwrite
        // Wh tile: 16384 floats, 16 float4 per thread, coalesced
#pragma unroll
        for (int q = 0; q < 16; q++) {
            const int idx = (t + q * 256) * 4;
            *(float4*)&wh_s[idx] = *(const float4*)&g_Wh[(size_t)j0 * CC + idx];
        }
        // dst tile (contiguous 256 floats)
        dst_s[t] = g_dst[j0 * HH + t];
        // adj tile: 32x64 ints; thread loads 8 (2x int4), stores scalar padded
        {
            const int il = t >> 3, jj = (t & 7) * 8;
            const int4 a0 = *(const int4*)&adj[(size_t)(i0 + il) * NN + j0 + jj];
            const int4 a1 = *(const int4*)&adj[(size_t)(i0 + il) * NN + j0 + jj + 4];
            int* dstp = &adj_s[il * 65 + jj];
            dstp[0] = a0.x; dstp[1] = a0.y; dstp[2] = a0.z; dstp[3] = a0.w;
            dstp[4] = a1.x; dstp[5] = a1.y; dstp[6] = a1.z; dstp[7] = a1.w;
        }
        __syncthreads();

        // Stage A: probabilities into p_s[(jj*4+h)*32 + il]
#pragma unroll
        for (int k = 0; k < 32; k++) {
            const int jj = jhalf * 32 + k;
            const float av = (float)adj_s[ilA * 65 + jj];
            float e = sA + dst_s[jj * 4 + hA];
            e = fmaxf(e, ALPHA * e);
            const float p = av * __expf(e - mA);
            p_s[(jj * 4 + hA) * 32 + ilA] = p;
            lsum += p;
        }
        __syncthreads();

        // Stage B: acc += p * wh   (f32x2 packed over il-pairs)
#pragma unroll 4
        for (int jj = 0; jj < TJ; jj++) {
            const float4 w  = *(const float4*)&wh_s[jj * 256 + hh * 64 + dg4 * 4];
            const float4 pa = *(const float4*)&p_s[(jj * 4 + hh) * 32 + il_g * 8];
            const float4 pb = *(const float4*)&p_s[(jj * 4 + hh) * 32 + il_g * 8 + 4];
            const uint64_t P01 = pack2(pa.x, pa.y);
            const uint64_t P23 = pack2(pa.z, pa.w);
            const uint64_t P45 = pack2(pb.x, pb.y);
            const uint64_t P67 = pack2(pb.z, pb.w);
            const uint64_t Wx = dup2(w.x), Wy = dup2(w.y), Wz = dup2(w.z), Ww = dup2(w.w);
            ffma2(acc[0][0], P01, Wx); ffma2(acc[0][1], P01, Wy);
            ffma2(acc[0][2], P01, Wz); ffma2(acc[0][3], P01, Ww);
            ffma2(acc[1][0], P23, Wx); ffma2(acc[1][1], P23, Wy);
            ffma2(acc[1][2], P23, Wz); ffma2(acc[1][3], P23, Ww);
            ffma2(acc[2][0], P45, Wx); ffma2(acc[2][1], P45, Wy);
            ffma2(acc[2][2], P45, Wz); ffma2(acc[2][3], P45, Ww);
            ffma2(acc[3][0], P67, Wx); ffma2(acc[3][1], P67, Wy);
            ffma2(acc[3][2], P67, Wz); ffma2(acc[3][3], P67, Ww);
        }
    }

    // reduce l over the 2 jhalf partials per (il,h)
    __syncthreads();
    lred[t] = lsum;
    __syncthreads();
    if (t < 128) {
        const int il = t & 31, h = t >> 5;
        ls[il * 4 + h] = lred[t] + lred[t + 128];
    }
    __syncthreads();

    // epilogue: normalize + store
#pragma unroll
    for (int rp = 0; rp < 4; rp++) {
        const int il0 = il_g * 8 + rp * 2;
        const float inv0 = 1.0f / ls[il0 * 4 + hh];
        const float inv1 = 1.0f / ls[(il0 + 1) * 4 + hh];
        float4 o0, o1;
        const float2 v0 = unpack2(acc[rp][0]);
        const float2 v1 = unpack2(acc[rp][1]);
        const float2 v2 = unpack2(acc[rp][2]);
        const float2 v3 = unpack2(acc[rp][3]);
        o0.x = v0.x * inv0; o0.y = v1.x * inv0; o0.z = v2.x * inv0; o0.w = v3.x * inv0;
        o1.x = v0.y * inv1; o1.y = v1.y * inv1; o1.z = v2.y * inv1; o1.w = v3.y * inv1;
        *(float4*)&out[(size_t)(i0 + il0) * CC + hh * 64 + dg4 * 4] = o0;
        *(float4*)&out[(size_t)(i0 + il0 + 1) * CC + hh * 64 + dg4 * 4] = o1;
    }
}

// ---------------------------------------------------------------------------
extern "C" void kernel_launch(void* const* d_in, const int* in_sizes, int n_in,
                              void* d_out, int out_size) {
    const float* h   = (const float*)d_in[0];
    const int*   adj = (const int*)d_in[1];
    const float* W   = (const float*)d_in[2];
    const float* b   = (const float*)d_in[3];
    const float* a   = (const float*)d_in[4];
    float* out = (float*)d_out;

    const int attn_smem = 27552 * (int)sizeof(float);  // ~107.6KB
    cudaFuncSetAttribute(attn_kernel, cudaFuncAttributeMaxDynamicSharedMemorySize, attn_smem);

    gemm_kernel<<<dim3(NN / 64, CC / 64), 256>>>(h, W, b);
    srcdst_kernel<<<NN / 8, 256>>>(a);
    gdmax_kernel<<<1, 256>>>();
    attn_kernel<<<NN / TI, 256, attn_smem>>>(adj, out);
}